// round 3
// baseline (speedup 1.0000x reference)
#include <cuda_runtime.h>
#include <cuda_bf16.h>

#define G   64
#define NN  1000
#define EE  8192
#define C   128
#define HID 256
#define NH  4
#define LNEPS 1e-5f

#define GNC4 (G*NN*32)   // float4 elements in a (G,N,C) buffer

// ---------------- scratch ----------------
__device__ float4 d_h4[GNC4];        // GEMM output h = X @ W
__device__ float4 d_act4[GNC4];      // tanh(aggregated) activation
__device__ float  d_dinv[G*NN];      // 1/sqrt(deg)
__device__ int    d_off[G*(NN+1)];   // CSR row offsets (by dst)
__device__ int2   d_csr[G*EE];       // per-edge {src, coef-bits}
__device__ float4 d_gpool4[G*32];    // pooled graph features (G,128)
__device__ float  d_qkv[G*3*C];
__device__ float  d_attn_o[G*C];
__device__ float  d_node[C];         // node_repr accumulator

// ---------------- kernels ----------------

// Per-graph: degree -> dinv, CSR by dst (counting sort, parallel scan),
// edge coef precompute.  Also zeroes this graph's pool slice.
__global__ void k_build(const int* __restrict__ ei) {
    int g = blockIdx.x;
    __shared__ int   cnt[NN+1];
    __shared__ float dinv_s[NN];
    __shared__ int   wsum[8];
    int tid = threadIdx.x;
    if (tid < 32) d_gpool4[g*32 + tid] = make_float4(0.f,0.f,0.f,0.f);
    for (int i = tid; i <= NN; i += 256) cnt[i] = 0;
    __syncthreads();
    const int* srcp = ei + g*2*EE;
    const int* dstp = srcp + EE;
    for (int e = tid; e < EE; e += 256)
        atomicAdd(&cnt[dstp[e] + 1], 1);
    __syncthreads();
    for (int i = tid; i < NN; i += 256) {
        float di = rsqrtf((float)cnt[i+1] + 1.0f);
        dinv_s[i] = di;
        d_dinv[g*NN + i] = di;
    }
    __syncthreads();
    // inclusive scan of cnt[0..NN]  (1001 elems, 4 per thread)
    int v[4]; int base = tid*4; int s = 0;
    #pragma unroll
    for (int j = 0; j < 4; j++) {
        v[j] = (base + j <= NN) ? cnt[base + j] : 0;
        s += v[j];
    }
    int lane = tid & 31, wid = tid >> 5;
    int sc = s;
    #pragma unroll
    for (int o = 1; o < 32; o <<= 1) {
        int t = __shfl_up_sync(0xffffffffu, sc, o);
        if (lane >= o) sc += t;
    }
    if (lane == 31) wsum[wid] = sc;
    __syncthreads();
    if (wid == 0) {
        int ws = (lane < 8) ? wsum[lane] : 0;
        #pragma unroll
        for (int o = 1; o < 8; o <<= 1) {
            int t = __shfl_up_sync(0xffffffffu, ws, o);
            if (lane >= o) ws += t;
        }
        if (lane < 8) wsum[lane] = ws;
    }
    __syncthreads();
    int run = sc - s + (wid > 0 ? wsum[wid-1] : 0);
    #pragma unroll
    for (int j = 0; j < 4; j++) {
        run += v[j];
        if (base + j <= NN) cnt[base + j] = run;
    }
    __syncthreads();
    for (int i = tid; i <= NN; i += 256)
        d_off[g*(NN+1) + i] = cnt[i];
    __syncthreads();
    for (int e = tid; e < EE; e += 256) {
        int sn = srcp[e], d = dstp[e];
        int pos = atomicAdd(&cnt[d], 1);
        float coef = dinv_s[sn] * dinv_s[d];
        d_csr[g*EE + pos] = make_int2(sn, __float_as_int(coef));
    }
}

// Y(=d_h4) = X @ W.  64 rows x 128 cols per block, fma.rn.f32x2 inner loop.
// X tile stored transposed (row-pairs natural for f32x2), W tile pre-duplicated
// so the inner loop has zero duplication MOVs: 4 LDS.64 + 2 LDS.128 + 16 FFMA2.
#define KT 32
__global__ void k_gemm(const float* __restrict__ Xext, int useAct,
                       const float* __restrict__ W) {
    const float* X = useAct ? (const float*)d_act4 : Xext;
    float* Y = (float*)d_h4;
    __shared__ __align__(16) float  Xs[KT][66];    // [k][row], padded
    __shared__ __align__(16) float2 Wd[KT][130];   // [k][col] = {w,w}, padded
    int tid = threadIdx.x;                          // 256 threads
    int row0 = blockIdx.x * 64;
    int cg = tid & 31;      // cols cg*4 .. cg*4+3
    int rg = tid >> 5;      // rows rg*8 .. rg*8+7  (4 row-pairs)
    unsigned long long acc[4][4];
    #pragma unroll
    for (int i = 0; i < 4; i++)
        #pragma unroll
        for (int c = 0; c < 4; c++) acc[i][c] = 0ull;

    for (int k0 = 0; k0 < 128; k0 += KT) {
        #pragma unroll
        for (int t = tid; t < 512; t += 256) {       // X tile 64x32 -> transposed
            int r = t >> 3, c4 = t & 7;
            float4 v = *(const float4*)&X[(row0 + r)*128 + k0 + c4*4];
            Xs[c4*4+0][r] = v.x; Xs[c4*4+1][r] = v.y;
            Xs[c4*4+2][r] = v.z; Xs[c4*4+3][r] = v.w;
        }
        #pragma unroll
        for (int t = tid; t < 1024; t += 256) {      // W tile 32x128 -> duplicated
            int r = t >> 5, c4 = t & 31;
            float4 v = *(const float4*)&W[(k0 + r)*128 + c4*4];
            Wd[r][c4*4+0] = make_float2(v.x, v.x);
            Wd[r][c4*4+1] = make_float2(v.y, v.y);
            Wd[r][c4*4+2] = make_float2(v.z, v.z);
            Wd[r][c4*4+3] = make_float2(v.w, v.w);
        }
        __syncthreads();
        #pragma unroll
        for (int kk = 0; kk < KT; kk++) {
            unsigned long long ap[4];
            #pragma unroll
            for (int i = 0; i < 4; i++)
                ap[i] = *(const unsigned long long*)&Xs[kk][rg*8 + 2*i];
            ulonglong2 wA = *(const ulonglong2*)&Wd[kk][cg*4];
            ulonglong2 wB = *(const ulonglong2*)&Wd[kk][cg*4 + 2];
            #pragma unroll
            for (int i = 0; i < 4; i++) {
                asm("fma.rn.f32x2 %0,%1,%2,%0;" : "+l"(acc[i][0]) : "l"(ap[i]), "l"(wA.x));
                asm("fma.rn.f32x2 %0,%1,%2,%0;" : "+l"(acc[i][1]) : "l"(ap[i]), "l"(wA.y));
                asm("fma.rn.f32x2 %0,%1,%2,%0;" : "+l"(acc[i][2]) : "l"(ap[i]), "l"(wB.x));
                asm("fma.rn.f32x2 %0,%1,%2,%0;" : "+l"(acc[i][3]) : "l"(ap[i]), "l"(wB.y));
            }
        }
        __syncthreads();
    }
    #pragma unroll
    for (int i = 0; i < 4; i++) {
        float2 v0 = *(float2*)&acc[i][0];
        float2 v1 = *(float2*)&acc[i][1];
        float2 v2 = *(float2*)&acc[i][2];
        float2 v3 = *(float2*)&acc[i][3];
        int r = row0 + rg*8 + 2*i;
        *(float4*)&Y[r*128 + cg*4]       = make_float4(v0.x, v1.x, v2.x, v3.x);
        *(float4*)&Y[(r+1)*128 + cg*4]   = make_float4(v0.y, v1.y, v2.y, v3.y);
    }
}

// Warp-per-node CSR gather + self-loop + bias + tanh.
//   layer1: write act;  layer2: atomic-accumulate into graph pool.
__global__ void k_gather(const float4* __restrict__ b4, int layer2) {
    int w = (blockIdx.x * blockDim.x + threadIdx.x) >> 5;
    int lane = threadIdx.x & 31;
    if (w >= G*NN) return;
    int g = w / NN, n = w % NN;
    float din = d_dinv[w];
    float s = din * din;
    float4 acc = d_h4[w*32 + lane];
    float4 bv = b4[lane];
    acc.x = acc.x*s + bv.x; acc.y = acc.y*s + bv.y;
    acc.z = acc.z*s + bv.z; acc.w = acc.w*s + bv.w;
    int start = d_off[g*(NN+1) + n];
    int end   = d_off[g*(NN+1) + n + 1];
    const int2* cs = d_csr + g*EE;
    const float4* hbase = d_h4 + (size_t)g*NN*32;
    for (int i = start; i < end; i++) {
        int2 e = __ldg(&cs[i]);
        float coef = __int_as_float(e.y);
        float4 v = hbase[e.x*32 + lane];
        acc.x += v.x*coef; acc.y += v.y*coef;
        acc.z += v.z*coef; acc.w += v.w*coef;
    }
    acc.x = tanhf(acc.x); acc.y = tanhf(acc.y);
    acc.z = tanhf(acc.z); acc.w = tanhf(acc.w);
    if (!layer2) d_act4[w*32 + lane] = acc;
    else         atomicAdd(&d_gpool4[g*32 + lane], acc);
}

// qkv = pooled @ in_w^T + in_b.
__global__ void k_qkv(const float* __restrict__ in_w, const float* __restrict__ in_b) {
    int g = blockIdx.x, j = threadIdx.x;
    __shared__ float gr[128];
    if (j < 128) gr[j] = ((const float*)d_gpool4)[g*128 + j];
    __syncthreads();
    float s = in_b[j];
    const float* w = in_w + j*128;
    #pragma unroll 8
    for (int k = 0; k < 128; k++) s += gr[k] * w[k];
    d_qkv[g*384 + j] = s;
}

// one block per head: scores -> softmax -> attn @ V.  Block 0 also zeroes d_node.
__global__ void k_attn() {
    int h = blockIdx.x, tid = threadIdx.x;
    if (h == 0 && tid < 128) d_node[tid] = 0.f;
    __shared__ float q[64][32], k[64][32], v[64][32], p[64][64];
    for (int t = tid; t < 64*32; t += 256) {
        int gg = t >> 5, dd = t & 31;
        q[gg][dd] = d_qkv[gg*384 + h*32 + dd];
        k[gg][dd] = d_qkv[gg*384 + 128 + h*32 + dd];
        v[gg][dd] = d_qkv[gg*384 + 256 + h*32 + dd];
    }
    __syncthreads();
    const float scale = 0.17677669529663687f;  // 1/sqrt(32)
    for (int t = tid; t < 64*64; t += 256) {
        int qi = t >> 6, ki = t & 63;
        float s = 0.f;
        #pragma unroll 8
        for (int dd = 0; dd < 32; dd++) s += q[qi][dd] * k[ki][dd];
        p[qi][ki] = s * scale;
    }
    __syncthreads();
    if (tid < 64) {
        float m = -1e30f;
        for (int ki = 0; ki < 64; ki++) m = fmaxf(m, p[tid][ki]);
        float sum = 0.f;
        for (int ki = 0; ki < 64; ki++) { float e = expf(p[tid][ki] - m); p[tid][ki] = e; sum += e; }
        float inv = 1.0f / sum;
        for (int ki = 0; ki < 64; ki++) p[tid][ki] *= inv;
    }
    __syncthreads();
    for (int t = tid; t < 64*32; t += 256) {
        int qi = t >> 5, dd = t & 31;
        float s = 0.f;
        #pragma unroll 8
        for (int ki = 0; ki < 64; ki++) s += p[qi][ki] * v[ki][dd];
        d_attn_o[qi*128 + h*32 + dd] = s;
    }
}

// out-proj + MLP + residual + layernorm + relu-sum into node_repr.
__global__ void k_head(const float* __restrict__ out_w, const float* __restrict__ out_b,
                       const float* __restrict__ mw1, const float* __restrict__ mb1,
                       const float* __restrict__ mw2, const float* __restrict__ mb2,
                       const float* __restrict__ lng, const float* __restrict__ lnb) {
    int g = blockIdx.x, c = threadIdx.x;
    __shared__ float o[128], xa[128], hid[256], red[128];
    o[c] = d_attn_o[g*128 + c];
    __syncthreads();
    float s = out_b[c];
    const float* w = out_w + c*128;
    #pragma unroll 8
    for (int k = 0; k < 128; k++) s += o[k] * w[k];
    xa[c] = s;
    __syncthreads();
    for (int hh = c; hh < 256; hh += 128) {
        float t = mb1[hh];
        #pragma unroll 8
        for (int k = 0; k < 128; k++) t += xa[k] * mw1[k*256 + hh];
        hid[hh] = fmaxf(t, 0.f);
    }
    __syncthreads();
    float m = mb2[c];
    #pragma unroll 8
    for (int k = 0; k < 256; k++) m += hid[k] * mw2[k*128 + c];
    float y = xa[c] + m;
    red[c] = y; __syncthreads();
    for (int o2 = 64; o2 > 0; o2 >>= 1) { if (c < o2) red[c] += red[c + o2]; __syncthreads(); }
    float mu = red[0] * (1.f/128.f);
    __syncthreads();
    float d = y - mu;
    red[c] = d * d; __syncthreads();
    for (int o2 = 64; o2 > 0; o2 >>= 1) { if (c < o2) red[c] += red[c + o2]; __syncthreads(); }
    float var = red[0] * (1.f/128.f);
    float yn = d * rsqrtf(var + LNEPS) * lng[c] + lnb[c];
    atomicAdd(&d_node[c], fmaxf(yn, 0.f));
}

__global__ void k_final(const float* __restrict__ lw, const float* __restrict__ lb,
                        float* __restrict__ out) {
    int t = threadIdx.x;
    __shared__ float nr[128];
    nr[t] = d_node[t];
    __syncthreads();
    if (t < 2) {
        float s = lb[t];
        for (int cc = 0; cc < 128; cc++) s += nr[cc] * lw[cc*2 + t];
        out[t] = s;
    }
}

// ---------------- launch ----------------
extern "C" void kernel_launch(void* const* d_in, const int* in_sizes, int n_in,
                              void* d_out, int out_size) {
    const float* x     = (const float*)d_in[0];
    const int*   ei    = (const int*)  d_in[1];
    const float* W0    = (const float*)d_in[2];
    const float* b0    = (const float*)d_in[3];
    const float* W1    = (const float*)d_in[4];
    const float* b1    = (const float*)d_in[5];
    const float* in_w  = (const float*)d_in[6];
    const float* in_b  = (const float*)d_in[7];
    const float* out_w = (const float*)d_in[8];
    const float* out_b = (const float*)d_in[9];
    const float* lng   = (const float*)d_in[10];
    const float* lnb   = (const float*)d_in[11];
    const float* mw1   = (const float*)d_in[12];
    const float* mb1   = (const float*)d_in[13];
    const float* mw2   = (const float*)d_in[14];
    const float* mb2   = (const float*)d_in[15];
    const float* lw    = (const float*)d_in[16];
    const float* lb    = (const float*)d_in[17];
    float* out = (float*)d_out;

    k_build<<<G, 256>>>(ei);

    // layer 1
    k_gemm<<<1000, 256>>>(x, 0, W0);
    k_gather<<<8000, 256>>>((const float4*)b0, 0);

    // layer 2
    k_gemm<<<1000, 256>>>(nullptr, 1, W1);
    k_gather<<<8000, 256>>>((const float4*)b1, 1);

    // head
    k_qkv<<<G, 384>>>(in_w, in_b);
    k_attn<<<NH, 256>>>();
    k_head<<<G, 128>>>(out_w, out_b, mw1, mb1, mw2, mb2, lng, lnb);
    k_final<<<1, 128>>>(lw, lb, out);
}

// round 7
// speedup vs baseline: 1.1845x; 1.1845x over previous
#include <cuda_runtime.h>
#include <cuda_bf16.h>
#include <cstdint>

#define G   64
#define NN  1000
#define EE  8192
#define C   128
#define HID 256
#define NH  4
#define LNEPS 1e-5f

#define GNC4 (G*NN*32)   // float4 elements in a (G,N,C) buffer

// ---------------- scratch ----------------
__device__ float4 d_h4[GNC4];        // GEMM output h = X @ W
__device__ float4 d_act4[GNC4];      // tanh(aggregated) activation
__device__ float  d_dinv[G*NN];      // 1/sqrt(deg)
__device__ int    d_off[G*(NN+1)];   // CSR row offsets (by dst)
__device__ int2   d_csr[G*EE];       // per-edge {src, coef-bits}
__device__ float4 d_gpool4[G*32];    // pooled graph features (G,128)
__device__ float  d_qkv[G*3*C];
__device__ float  d_attn_o[G*C];
__device__ float  d_node[C];         // node_repr accumulator

__device__ __forceinline__ uint32_t smem_u32(const void* p) {
    uint32_t a;
    asm("{ .reg .u64 t; cvta.to.shared.u64 t, %1; cvt.u32.u64 %0, t; }" : "=r"(a) : "l"(p));
    return a;
}

// pack two bf16 into one 32-bit word (portable across CUDA header versions)
__device__ __forceinline__ uint32_t pack_bf16x2(__nv_bfloat16 a, __nv_bfloat16 b) {
    uint16_t ua = *(uint16_t*)&a, ub = *(uint16_t*)&b;
    return (uint32_t)ua | ((uint32_t)ub << 16);
}

// ---------------- kernels ----------------

// Per-graph: degree -> dinv, CSR by dst (counting sort, parallel scan),
// edge coef precompute.  Also zeroes this graph's pool slice.
__global__ void k_build(const int* __restrict__ ei) {
    int g = blockIdx.x;
    __shared__ int   cnt[NN+1];
    __shared__ float dinv_s[NN];
    __shared__ int   wsum[8];
    int tid = threadIdx.x;
    if (tid < 32) d_gpool4[g*32 + tid] = make_float4(0.f,0.f,0.f,0.f);
    for (int i = tid; i <= NN; i += 256) cnt[i] = 0;
    __syncthreads();
    const int* srcp = ei + g*2*EE;
    const int* dstp = srcp + EE;
    for (int e = tid; e < EE; e += 256)
        atomicAdd(&cnt[dstp[e] + 1], 1);
    __syncthreads();
    for (int i = tid; i < NN; i += 256) {
        float di = rsqrtf((float)cnt[i+1] + 1.0f);
        dinv_s[i] = di;
        d_dinv[g*NN + i] = di;
    }
    __syncthreads();
    int v[4]; int base = tid*4; int s = 0;
    #pragma unroll
    for (int j = 0; j < 4; j++) {
        v[j] = (base + j <= NN) ? cnt[base + j] : 0;
        s += v[j];
    }
    int lane = tid & 31, wid = tid >> 5;
    int sc = s;
    #pragma unroll
    for (int o = 1; o < 32; o <<= 1) {
        int t = __shfl_up_sync(0xffffffffu, sc, o);
        if (lane >= o) sc += t;
    }
    if (lane == 31) wsum[wid] = sc;
    __syncthreads();
    if (wid == 0) {
        int ws = (lane < 8) ? wsum[lane] : 0;
        #pragma unroll
        for (int o = 1; o < 8; o <<= 1) {
            int t = __shfl_up_sync(0xffffffffu, ws, o);
            if (lane >= o) ws += t;
        }
        if (lane < 8) wsum[lane] = ws;
    }
    __syncthreads();
    int run = sc - s + (wid > 0 ? wsum[wid-1] : 0);
    #pragma unroll
    for (int j = 0; j < 4; j++) {
        run += v[j];
        if (base + j <= NN) cnt[base + j] = run;
    }
    __syncthreads();
    for (int i = tid; i <= NN; i += 256)
        d_off[g*(NN+1) + i] = cnt[i];
    __syncthreads();
    for (int e = tid; e < EE; e += 256) {
        int sn = srcp[e], d = dstp[e];
        int pos = atomicAdd(&cnt[d], 1);
        float coef = dinv_s[sn] * dinv_s[d];
        d_csr[g*EE + pos] = make_int2(sn, __float_as_int(coef));
    }
}

// ---- mma.sync bf16 split-precision GEMM:  Y = X @ W  (fp32 in/out) ----
// Tile: 128 rows x 128 cols x K=128.  x = hi + lo (bf16); terms HH + HL + LH.
// 8 warps; warp w computes rows 16w..16w+15, all 128 cols.
#define AS 136                         // padded smem row stride (bf16 units)
#define SM_TILE (128*AS)               // one 128x128 bf16 tile (padded)

__global__ void __launch_bounds__(256)
k_gemm_mma(const float* __restrict__ Xext, int useAct, const float* __restrict__ W) {
    const float* X = useAct ? (const float*)d_act4 : Xext;
    float* Y = (float*)d_h4;
    extern __shared__ __align__(16) __nv_bfloat16 smem[];
    __nv_bfloat16* Ahi = smem;
    __nv_bfloat16* Alo = Ahi + SM_TILE;
    __nv_bfloat16* Bhi = Alo + SM_TILE;
    __nv_bfloat16* Blo = Bhi + SM_TILE;
    int tid = threadIdx.x, wid = tid >> 5, lane = tid & 31;
    int row0 = blockIdx.x * 128;

    // stage A (X rows): hi/lo bf16, padded row-major [r][k]
    for (int idx = tid; idx < 128*64; idx += 256) {
        int r = idx >> 6, kp = idx & 63;
        float2 v = *(const float2*)&X[(row0 + r)*128 + kp*2];
        __nv_bfloat16 hx = __float2bfloat16_rn(v.x);
        __nv_bfloat16 hy = __float2bfloat16_rn(v.y);
        __nv_bfloat16 lx = __float2bfloat16_rn(v.x - __bfloat162float(hx));
        __nv_bfloat16 ly = __float2bfloat16_rn(v.y - __bfloat162float(hy));
        *(uint32_t*)&Ahi[r*AS + kp*2] = pack_bf16x2(hx, hy);
        *(uint32_t*)&Alo[r*AS + kp*2] = pack_bf16x2(lx, ly);
    }
    // stage B (W): [k][n] row-major (k rows), padded
    for (int idx = tid; idx < 128*64; idx += 256) {
        int k = idx >> 6, np = idx & 63;
        float2 v = *(const float2*)&W[k*128 + np*2];
        __nv_bfloat16 hx = __float2bfloat16_rn(v.x);
        __nv_bfloat16 hy = __float2bfloat16_rn(v.y);
        __nv_bfloat16 lx = __float2bfloat16_rn(v.x - __bfloat162float(hx));
        __nv_bfloat16 ly = __float2bfloat16_rn(v.y - __bfloat162float(hy));
        *(uint32_t*)&Bhi[k*AS + np*2] = pack_bf16x2(hx, hy);
        *(uint32_t*)&Blo[k*AS + np*2] = pack_bf16x2(lx, ly);
    }
    __syncthreads();

    float acc[16][4];
    #pragma unroll
    for (int i = 0; i < 16; i++)
        #pragma unroll
        for (int j = 0; j < 4; j++) acc[i][j] = 0.f;

    int arow = wid*16 + (lane & 15);          // ldmatrix A row for this lane
    int acol8 = (lane >> 4) * 8;              // k sub-block
    int bk = (lane & 7) + ((lane >> 3) & 1) * 8;  // ldmatrix B k-row
    int bn8 = (lane >> 4) * 8;                // n sub-block

    #pragma unroll
    for (int term = 0; term < 3; term++) {
        const __nv_bfloat16* Aseg = (term < 2) ? Ahi : Alo;
        const __nv_bfloat16* Bseg = (term == 1) ? Blo : Bhi;
        #pragma unroll
        for (int k0 = 0; k0 < 128; k0 += 16) {
            uint32_t a0, a1, a2, a3;
            uint32_t aaddr = smem_u32(&Aseg[arow*AS + k0 + acol8]);
            asm volatile("ldmatrix.sync.aligned.m8n8.x4.shared.b16 {%0,%1,%2,%3}, [%4];"
                : "=r"(a0), "=r"(a1), "=r"(a2), "=r"(a3) : "r"(aaddr));
            #pragma unroll
            for (int nt = 0; nt < 16; nt += 2) {
                uint32_t b0, b1, b2, b3;
                uint32_t baddr = smem_u32(&Bseg[(k0 + bk)*AS + nt*8 + bn8]);
                asm volatile("ldmatrix.sync.aligned.m8n8.x4.trans.shared.b16 {%0,%1,%2,%3}, [%4];"
                    : "=r"(b0), "=r"(b1), "=r"(b2), "=r"(b3) : "r"(baddr));
                asm volatile("mma.sync.aligned.m16n8k16.row.col.f32.bf16.bf16.f32 "
                    "{%0,%1,%2,%3},{%4,%5,%6,%7},{%8,%9},{%0,%1,%2,%3};"
                    : "+f"(acc[nt][0]), "+f"(acc[nt][1]), "+f"(acc[nt][2]), "+f"(acc[nt][3])
                    : "r"(a0), "r"(a1), "r"(a2), "r"(a3), "r"(b0), "r"(b1));
                asm volatile("mma.sync.aligned.m16n8k16.row.col.f32.bf16.bf16.f32 "
                    "{%0,%1,%2,%3},{%4,%5,%6,%7},{%8,%9},{%0,%1,%2,%3};"
                    : "+f"(acc[nt+1][0]), "+f"(acc[nt+1][1]), "+f"(acc[nt+1][2]), "+f"(acc[nt+1][3])
                    : "r"(a0), "r"(a1), "r"(a2), "r"(a3), "r"(b2), "r"(b3));
            }
        }
    }

    // epilogue: c0,c1 -> (row lane/4, cols (lane%4)*2); c2,c3 -> row+8
    int r_lo = row0 + wid*16 + (lane >> 2);
    int cbase = (lane & 3) * 2;
    #pragma unroll
    for (int nt = 0; nt < 16; nt++) {
        *(float2*)&Y[r_lo*128 + nt*8 + cbase]     = make_float2(acc[nt][0], acc[nt][1]);
        *(float2*)&Y[(r_lo+8)*128 + nt*8 + cbase] = make_float2(acc[nt][2], acc[nt][3]);
    }
}

// Warp-per-node CSR gather + self-loop + bias + tanh.
//   layer1: write act;  layer2: atomic-accumulate into graph pool.
__global__ void k_gather(const float4* __restrict__ b4, int layer2) {
    int w = (blockIdx.x * blockDim.x + threadIdx.x) >> 5;
    int lane = threadIdx.x & 31;
    if (w >= G*NN) return;
    int g = w / NN, n = w % NN;
    float din = d_dinv[w];
    float s = din * din;
    float4 acc = d_h4[w*32 + lane];
    float4 bv = b4[lane];
    acc.x = acc.x*s + bv.x; acc.y = acc.y*s + bv.y;
    acc.z = acc.z*s + bv.z; acc.w = acc.w*s + bv.w;
    int start = d_off[g*(NN+1) + n];
    int end   = d_off[g*(NN+1) + n + 1];
    const int2* cs = d_csr + g*EE;
    const float4* hbase = d_h4 + (size_t)g*NN*32;
    for (int i = start; i < end; i++) {
        int2 e = __ldg(&cs[i]);
        float coef = __int_as_float(e.y);
        float4 v = hbase[e.x*32 + lane];
        acc.x += v.x*coef; acc.y += v.y*coef;
        acc.z += v.z*coef; acc.w += v.w*coef;
    }
    acc.x = tanhf(acc.x); acc.y = tanhf(acc.y);
    acc.z = tanhf(acc.z); acc.w = tanhf(acc.w);
    if (!layer2) d_act4[w*32 + lane] = acc;
    else         atomicAdd(&d_gpool4[g*32 + lane], acc);
}

// qkv = pooled @ in_w^T + in_b.
__global__ void k_qkv(const float* __restrict__ in_w, const float* __restrict__ in_b) {
    int g = blockIdx.x, j = threadIdx.x;
    __shared__ float gr[128];
    if (j < 128) gr[j] = ((const float*)d_gpool4)[g*128 + j];
    __syncthreads();
    float s = in_b[j];
    const float* w = in_w + j*128;
    #pragma unroll 8
    for (int k = 0; k < 128; k++) s += gr[k] * w[k];
    d_qkv[g*384 + j] = s;
}

// one block per head: scores -> softmax -> attn @ V.  Block 0 also zeroes d_node.
__global__ void k_attn() {
    int h = blockIdx.x, tid = threadIdx.x;
    if (h == 0 && tid < 128) d_node[tid] = 0.f;
    __shared__ float q[64][32], k[64][32], v[64][32], p[64][64];
    for (int t = tid; t < 64*32; t += 256) {
        int gg = t >> 5, dd = t & 31;
        q[gg][dd] = d_qkv[gg*384 + h*32 + dd];
        k[gg][dd] = d_qkv[gg*384 + 128 + h*32 + dd];
        v[gg][dd] = d_qkv[gg*384 + 256 + h*32 + dd];
    }
    __syncthreads();
    const float scale = 0.17677669529663687f;
    for (int t = tid; t < 64*64; t += 256) {
        int qi = t >> 6, ki = t & 63;
        float s = 0.f;
        #pragma unroll 8
        for (int dd = 0; dd < 32; dd++) s += q[qi][dd] * k[ki][dd];
        p[qi][ki] = s * scale;
    }
    __syncthreads();
    if (tid < 64) {
        float m = -1e30f;
        for (int ki = 0; ki < 64; ki++) m = fmaxf(m, p[tid][ki]);
        float sum = 0.f;
        for (int ki = 0; ki < 64; ki++) { float e = expf(p[tid][ki] - m); p[tid][ki] = e; sum += e; }
        float inv = 1.0f / sum;
        for (int ki = 0; ki < 64; ki++) p[tid][ki] *= inv;
    }
    __syncthreads();
    for (int t = tid; t < 64*32; t += 256) {
        int qi = t >> 5, dd = t & 31;
        float s = 0.f;
        #pragma unroll 8
        for (int ki = 0; ki < 64; ki++) s += p[qi][ki] * v[ki][dd];
        d_attn_o[qi*128 + h*32 + dd] = s;
    }
}

// out-proj + MLP + residual + layernorm + relu-sum into node_repr.
__global__ void k_head(const float* __restrict__ out_w, const float* __restrict__ out_b,
                       const float* __restrict__ mw1, const float* __restrict__ mb1,
                       const float* __restrict__ mw2, const float* __restrict__ mb2,
                       const float* __restrict__ lng, const float* __restrict__ lnb) {
    int g = blockIdx.x, c = threadIdx.x;
    __shared__ float o[128], xa[128], hid[256], red[128];
    o[c] = d_attn_o[g*128 + c];
    __syncthreads();
    float s = out_b[c];
    const float* w = out_w + c*128;
    #pragma unroll 8
    for (int k = 0; k < 128; k++) s += o[k] * w[k];
    xa[c] = s;
    __syncthreads();
    for (int hh = c; hh < 256; hh += 128) {
        float t = mb1[hh];
        #pragma unroll 8
        for (int k = 0; k < 128; k++) t += xa[k] * mw1[k*256 + hh];
        hid[hh] = fmaxf(t, 0.f);
    }
    __syncthreads();
    float m = mb2[c];
    #pragma unroll 8
    for (int k = 0; k < 256; k++) m += hid[k] * mw2[k*128 + c];
    float y = xa[c] + m;
    red[c] = y; __syncthreads();
    for (int o2 = 64; o2 > 0; o2 >>= 1) { if (c < o2) red[c] += red[c + o2]; __syncthreads(); }
    float mu = red[0] * (1.f/128.f);
    __syncthreads();
    float d = y - mu;
    red[c] = d * d; __syncthreads();
    for (int o2 = 64; o2 > 0; o2 >>= 1) { if (c < o2) red[c] += red[c + o2]; __syncthreads(); }
    float var = red[0] * (1.f/128.f);
    float yn = d * rsqrtf(var + LNEPS) * lng[c] + lnb[c];
    atomicAdd(&d_node[c], fmaxf(yn, 0.f));
}

__global__ void k_final(const float* __restrict__ lw, const float* __restrict__ lb,
                        float* __restrict__ out) {
    int t = threadIdx.x;
    __shared__ float nr[128];
    nr[t] = d_node[t];
    __syncthreads();
    if (t < 2) {
        float s = lb[t];
        for (int cc = 0; cc < 128; cc++) s += nr[cc] * lw[cc*2 + t];
        out[t] = s;
    }
}

// ---------------- launch ----------------
extern "C" void kernel_launch(void* const* d_in, const int* in_sizes, int n_in,
                              void* d_out, int out_size) {
    const float* x     = (const float*)d_in[0];
    const int*   ei    = (const int*)  d_in[1];
    const float* W0    = (const float*)d_in[2];
    const float* b0    = (const float*)d_in[3];
    const float* W1    = (const float*)d_in[4];
    const float* b1    = (const float*)d_in[5];
    const float* in_w  = (const float*)d_in[6];
    const float* in_b  = (const float*)d_in[7];
    const float* out_w = (const float*)d_in[8];
    const float* out_b = (const float*)d_in[9];
    const float* lng   = (const float*)d_in[10];
    const float* lnb   = (const float*)d_in[11];
    const float* mw1   = (const float*)d_in[12];
    const float* mb1   = (const float*)d_in[13];
    const float* mw2   = (const float*)d_in[14];
    const float* mb2   = (const float*)d_in[15];
    const float* lw    = (const float*)d_in[16];
    const float* lb    = (const float*)d_in[17];
    float* out = (float*)d_out;

    const int gemm_smem = 4 * SM_TILE * (int)sizeof(__nv_bfloat16);  // 139264 B
    static int smem_set = 0;
    if (!smem_set) {
        cudaFuncSetAttribute(k_gemm_mma, cudaFuncAttributeMaxDynamicSharedMemorySize, gemm_smem);
        smem_set = 1;
    }

    k_build<<<G, 256>>>(ei);

    // layer 1
    k_gemm_mma<<<500, 256, gemm_smem>>>(x, 0, W0);
    k_gather<<<8000, 256>>>((const float4*)b0, 0);

    // layer 2
    k_gemm_mma<<<500, 256, gemm_smem>>>(nullptr, 1, W1);
    k_gather<<<8000, 256>>>((const float4*)b1, 1);

    // head
    k_qkv<<<G, 384>>>(in_w, in_b);
    k_attn<<<NH, 256>>>();
    k_head<<<G, 128>>>(out_w, out_b, mw1, mb1, mw2, mb2, lng, lnb);
    k_final<<<1, 128>>>(lw, lb, out);
}

// round 8
// speedup vs baseline: 1.4326x; 1.2094x over previous
#include <cuda_runtime.h>
#include <cuda_bf16.h>
#include <cstdint>

#define G   64
#define NN  1000
#define EE  8192
#define C   128
#define HID 256
#define NH  4
#define LNEPS 1e-5f

#define GNC4 (G*NN*32)   // float4 elements in a (G,N,C) buffer

// ---------------- scratch ----------------
__device__ float4 d_h4[GNC4];        // GEMM output h = X @ W
__device__ float4 d_act4[GNC4];      // tanh(aggregated) activation
__device__ float  d_dinv[G*NN];      // 1/sqrt(deg)
__device__ int    d_off[G*(NN+1)];   // CSR row offsets (by dst)
__device__ int2   d_csr[G*EE];       // per-edge {src, coef-bits}
__device__ float4 d_gpool4[G*32];    // pooled graph features (G,128)
__device__ float  d_qkv[G*3*C];
__device__ float  d_attn_o[G*C];
__device__ float  d_node[C];         // node_repr accumulator
// W in mma B-fragment layout: [weight][hi/lo][(k0*8+ntp)*32+lane] (uint4 each)
__device__ uint4  d_wf[2][2][8*8*32];

__device__ __forceinline__ uint32_t smem_u32(const void* p) {
    uint32_t a;
    asm("{ .reg .u64 t; cvta.to.shared.u64 t, %1; cvt.u32.u64 %0, t; }" : "=r"(a) : "l"(p));
    return a;
}
__device__ __forceinline__ uint32_t pack_bf16x2(__nv_bfloat16 a, __nv_bfloat16 b) {
    uint16_t ua = *(uint16_t*)&a, ub = *(uint16_t*)&b;
    return (uint32_t)ua | ((uint32_t)ub << 16);
}

// ---------------- kernels ----------------

// Per-graph: degree -> dinv, CSR by dst (counting sort, parallel scan),
// edge coef precompute.  Also zeroes this graph's pool slice.
__global__ void k_build(const int* __restrict__ ei) {
    int g = blockIdx.x;
    __shared__ int   cnt[NN+1];
    __shared__ float dinv_s[NN];
    __shared__ int   wsum[8];
    int tid = threadIdx.x;
    if (tid < 32) d_gpool4[g*32 + tid] = make_float4(0.f,0.f,0.f,0.f);
    for (int i = tid; i <= NN; i += 256) cnt[i] = 0;
    __syncthreads();
    const int* srcp = ei + g*2*EE;
    const int* dstp = srcp + EE;
    for (int e = tid; e < EE; e += 256)
        atomicAdd(&cnt[dstp[e] + 1], 1);
    __syncthreads();
    for (int i = tid; i < NN; i += 256) {
        float di = rsqrtf((float)cnt[i+1] + 1.0f);
        dinv_s[i] = di;
        d_dinv[g*NN + i] = di;
    }
    __syncthreads();
    int v[4]; int base = tid*4; int s = 0;
    #pragma unroll
    for (int j = 0; j < 4; j++) {
        v[j] = (base + j <= NN) ? cnt[base + j] : 0;
        s += v[j];
    }
    int lane = tid & 31, wid = tid >> 5;
    int sc = s;
    #pragma unroll
    for (int o = 1; o < 32; o <<= 1) {
        int t = __shfl_up_sync(0xffffffffu, sc, o);
        if (lane >= o) sc += t;
    }
    if (lane == 31) wsum[wid] = sc;
    __syncthreads();
    if (wid == 0) {
        int ws = (lane < 8) ? wsum[lane] : 0;
        #pragma unroll
        for (int o = 1; o < 8; o <<= 1) {
            int t = __shfl_up_sync(0xffffffffu, ws, o);
            if (lane >= o) ws += t;
        }
        if (lane < 8) wsum[lane] = ws;
    }
    __syncthreads();
    int run = sc - s + (wid > 0 ? wsum[wid-1] : 0);
    #pragma unroll
    for (int j = 0; j < 4; j++) {
        run += v[j];
        if (base + j <= NN) cnt[base + j] = run;
    }
    __syncthreads();
    for (int i = tid; i <= NN; i += 256)
        d_off[g*(NN+1) + i] = cnt[i];
    __syncthreads();
    for (int e = tid; e < EE; e += 256) {
        int sn = srcp[e], d = dstp[e];
        int pos = atomicAdd(&cnt[d], 1);
        float coef = dinv_s[sn] * dinv_s[d];
        d_csr[g*EE + pos] = make_int2(sn, __float_as_int(coef));
    }
}

// Pre-bake W0/W1 into mma B-fragment layout (hi/lo bf16 split).
// For m16n8k16 row.col: lane l of fragment (k0, nt): n = nt*8 + l/4,
// b0 = {B[k0*16+(l%4)*2][n], B[..+1][n]}, b1 = same with k+8.
// Stored as uint4 per (k0, ntp= nt/2, lane): {b0(nt0), b1(nt0), b0(nt1), b1(nt1)}.
__global__ void k_wprep(const float* __restrict__ W0, const float* __restrict__ W1) {
    int idx = blockIdx.x * blockDim.x + threadIdx.x;   // 2*8*8*32 = 4096
    int lane = idx & 31;
    int ntp  = (idx >> 5) & 7;
    int k0   = (idx >> 8) & 7;
    int widx = idx >> 11;
    const float* W = widx ? W1 : W0;
    int kb = k0*16 + (lane & 3)*2;
    uint4 hi, lo;
    uint32_t* hp = (uint32_t*)&hi;
    uint32_t* lp = (uint32_t*)&lo;
    #pragma unroll
    for (int half = 0; half < 2; half++) {          // nt0, nt1
        int n = (ntp*2 + half)*8 + (lane >> 2);
        #pragma unroll
        for (int kk = 0; kk < 2; kk++) {            // b0 (k), b1 (k+8)
            float v0 = W[(kb + kk*8    )*128 + n];
            float v1 = W[(kb + kk*8 + 1)*128 + n];
            __nv_bfloat16 h0 = __float2bfloat16_rn(v0);
            __nv_bfloat16 h1 = __float2bfloat16_rn(v1);
            __nv_bfloat16 l0 = __float2bfloat16_rn(v0 - __bfloat162float(h0));
            __nv_bfloat16 l1 = __float2bfloat16_rn(v1 - __bfloat162float(h1));
            hp[half*2 + kk] = pack_bf16x2(h0, h1);
            lp[half*2 + kk] = pack_bf16x2(l0, l1);
        }
    }
    int fo = (k0*8 + ntp)*32 + lane;
    d_wf[widx][0][fo] = hi;
    d_wf[widx][1][fo] = lo;
}

// ---- mma.sync bf16 split-precision GEMM:  Y = X @ W  (fp32 in/out) ----
// 64-row tile (grid 1000), 8 warps: warp covers 16 rows x 64 cols.
// A hi/lo staged in smem (ldmatrix); B fragments direct from d_wf (L2).
// Per k-step: load frags once, issue all 3 split terms (HH, HL, LH).
#define AS 136
__global__ void __launch_bounds__(256, 2)
k_gemm_mma(const float* __restrict__ Xext, int useAct, int widx) {
    const float* X = useAct ? (const float*)d_act4 : Xext;
    float* Y = (float*)d_h4;
    __shared__ __align__(16) __nv_bfloat16 Ahi[64*AS];
    __shared__ __align__(16) __nv_bfloat16 Alo[64*AS];
    int tid = threadIdx.x, wid = tid >> 5, lane = tid & 31;
    int row0 = blockIdx.x * 64;

    // stage A (64x128) hi/lo
    for (int idx = tid; idx < 64*32; idx += 256) {
        int r = idx >> 5, kp = idx & 31;            // 4 floats per thread
        float4 v = *(const float4*)&X[(row0 + r)*128 + kp*4];
        __nv_bfloat16 h0 = __float2bfloat16_rn(v.x), h1 = __float2bfloat16_rn(v.y);
        __nv_bfloat16 h2 = __float2bfloat16_rn(v.z), h3 = __float2bfloat16_rn(v.w);
        *(uint32_t*)&Ahi[r*AS + kp*4]     = pack_bf16x2(h0, h1);
        *(uint32_t*)&Ahi[r*AS + kp*4 + 2] = pack_bf16x2(h2, h3);
        *(uint32_t*)&Alo[r*AS + kp*4]     = pack_bf16x2(
            __float2bfloat16_rn(v.x - __bfloat162float(h0)),
            __float2bfloat16_rn(v.y - __bfloat162float(h1)));
        *(uint32_t*)&Alo[r*AS + kp*4 + 2] = pack_bf16x2(
            __float2bfloat16_rn(v.z - __bfloat162float(h2)),
            __float2bfloat16_rn(v.w - __bfloat162float(h3)));
    }
    __syncthreads();

    float acc[8][4];
    #pragma unroll
    for (int i = 0; i < 8; i++)
        #pragma unroll
        for (int j = 0; j < 4; j++) acc[i][j] = 0.f;

    int arow = (wid >> 1)*16 + (lane & 15);
    int acol8 = (lane >> 4) * 8;
    int ntp0 = (wid & 1) * 4;                  // 4 nt-pairs = 64 cols
    const uint4* BH = d_wf[widx][0];
    const uint4* BL = d_wf[widx][1];

    #pragma unroll
    for (int k0 = 0; k0 < 8; k0++) {
        // B fragments for this k-step (global, L2-resident)
        uint4 bh[4], bl[4];
        #pragma unroll
        for (int p = 0; p < 4; p++) {
            int fo = (k0*8 + ntp0 + p)*32 + lane;
            bh[p] = __ldg(&BH[fo]);
            bl[p] = __ldg(&BL[fo]);
        }
        // A fragments hi/lo
        uint32_t ah0, ah1, ah2, ah3, al0, al1, al2, al3;
        uint32_t aaddr = smem_u32(&Ahi[arow*AS + k0*16 + acol8]);
        asm volatile("ldmatrix.sync.aligned.m8n8.x4.shared.b16 {%0,%1,%2,%3}, [%4];"
            : "=r"(ah0), "=r"(ah1), "=r"(ah2), "=r"(ah3) : "r"(aaddr));
        uint32_t laddr = smem_u32(&Alo[arow*AS + k0*16 + acol8]);
        asm volatile("ldmatrix.sync.aligned.m8n8.x4.shared.b16 {%0,%1,%2,%3}, [%4];"
            : "=r"(al0), "=r"(al1), "=r"(al2), "=r"(al3) : "r"(laddr));

        #define MMA(ACC, A0,A1,A2,A3, B0,B1) \
            asm volatile("mma.sync.aligned.m16n8k16.row.col.f32.bf16.bf16.f32 " \
                "{%0,%1,%2,%3},{%4,%5,%6,%7},{%8,%9},{%0,%1,%2,%3};" \
                : "+f"(ACC[0]), "+f"(ACC[1]), "+f"(ACC[2]), "+f"(ACC[3]) \
                : "r"(A0), "r"(A1), "r"(A2), "r"(A3), "r"(B0), "r"(B1))
        #pragma unroll
        for (int p = 0; p < 4; p++) {
            MMA(acc[p*2],   ah0,ah1,ah2,ah3, bh[p].x, bh[p].y);   // HH nt0
            MMA(acc[p*2+1], ah0,ah1,ah2,ah3, bh[p].z, bh[p].w);   // HH nt1
            MMA(acc[p*2],   ah0,ah1,ah2,ah3, bl[p].x, bl[p].y);   // HL nt0
            MMA(acc[p*2+1], ah0,ah1,ah2,ah3, bl[p].z, bl[p].w);   // HL nt1
            MMA(acc[p*2],   al0,al1,al2,al3, bh[p].x, bh[p].y);   // LH nt0
            MMA(acc[p*2+1], al0,al1,al2,al3, bh[p].z, bh[p].w);   // LH nt1
        }
        #undef MMA
    }

    int r_lo = row0 + (wid >> 1)*16 + (lane >> 2);
    int cb = ntp0*16 + (lane & 3)*2;
    #pragma unroll
    for (int nt = 0; nt < 8; nt++) {
        *(float2*)&Y[r_lo*128 + cb + nt*8]     = make_float2(acc[nt][0], acc[nt][1]);
        *(float2*)&Y[(r_lo+8)*128 + cb + nt*8] = make_float2(acc[nt][2], acc[nt][3]);
    }
}

// Warp-per-node CSR gather + self-loop + bias + tanh.
__global__ void k_gather(const float4* __restrict__ b4, int layer2) {
    int w = (blockIdx.x * blockDim.x + threadIdx.x) >> 5;
    int lane = threadIdx.x & 31;
    if (w >= G*NN) return;
    int g = w / NN, n = w % NN;
    float din = d_dinv[w];
    float s = din * din;
    float4 acc = d_h4[w*32 + lane];
    float4 bv = b4[lane];
    acc.x = acc.x*s + bv.x; acc.y = acc.y*s + bv.y;
    acc.z = acc.z*s + bv.z; acc.w = acc.w*s + bv.w;
    int start = d_off[g*(NN+1) + n];
    int end   = d_off[g*(NN+1) + n + 1];
    const int2* cs = d_csr + g*EE;
    const float4* hbase = d_h4 + (size_t)g*NN*32;
    for (int i = start; i < end; i++) {
        int2 e = __ldg(&cs[i]);
        float coef = __int_as_float(e.y);
        float4 v = hbase[e.x*32 + lane];
        acc.x += v.x*coef; acc.y += v.y*coef;
        acc.z += v.z*coef; acc.w += v.w*coef;
    }
    acc.x = tanhf(acc.x); acc.y = tanhf(acc.y);
    acc.z = tanhf(acc.z); acc.w = tanhf(acc.w);
    if (!layer2) d_act4[w*32 + lane] = acc;
    else         atomicAdd(&d_gpool4[g*32 + lane], acc);
}

// qkv = pooled @ in_w^T + in_b.
__global__ void k_qkv(const float* __restrict__ in_w, const float* __restrict__ in_b) {
    int g = blockIdx.x, j = threadIdx.x;
    __shared__ float gr[128];
    if (j < 128) gr[j] = ((const float*)d_gpool4)[g*128 + j];
    __syncthreads();
    float s = in_b[j];
    const float* w = in_w + j*128;
    #pragma unroll 8
    for (int k = 0; k < 128; k++) s += gr[k] * w[k];
    d_qkv[g*384 + j] = s;
}

// one block per head: scores -> softmax -> attn @ V.  Block 0 also zeroes d_node.
__global__ void k_attn() {
    int h = blockIdx.x, tid = threadIdx.x;
    if (h == 0 && tid < 128) d_node[tid] = 0.f;
    __shared__ float q[64][32], k[64][32], v[64][32], p[64][64];
    for (int t = tid; t < 64*32; t += 256) {
        int gg = t >> 5, dd = t & 31;
        q[gg][dd] = d_qkv[gg*384 + h*32 + dd];
        k[gg][dd] = d_qkv[gg*384 + 128 + h*32 + dd];
        v[gg][dd] = d_qkv[gg*384 + 256 + h*32 + dd];
    }
    __syncthreads();
    const float scale = 0.17677669529663687f;
    for (int t = tid; t < 64*64; t += 256) {
        int qi = t >> 6, ki = t & 63;
        float s = 0.f;
        #pragma unroll 8
        for (int dd = 0; dd < 32; dd++) s += q[qi][dd] * k[ki][dd];
        p[qi][ki] = s * scale;
    }
    __syncthreads();
    if (tid < 64) {
        float m = -1e30f;
        for (int ki = 0; ki < 64; ki++) m = fmaxf(m, p[tid][ki]);
        float sum = 0.f;
        for (int ki = 0; ki < 64; ki++) { float e = expf(p[tid][ki] - m); p[tid][ki] = e; sum += e; }
        float inv = 1.0f / sum;
        for (int ki = 0; ki < 64; ki++) p[tid][ki] *= inv;
    }
    __syncthreads();
    for (int t = tid; t < 64*32; t += 256) {
        int qi = t >> 5, dd = t & 31;
        float s = 0.f;
        #pragma unroll 8
        for (int ki = 0; ki < 64; ki++) s += p[qi][ki] * v[ki][dd];
        d_attn_o[qi*128 + h*32 + dd] = s;
    }
}

// out-proj + MLP + residual + layernorm + relu-sum into node_repr.
__global__ void k_head(const float* __restrict__ out_w, const float* __restrict__ out_b,
                       const float* __restrict__ mw1, const float* __restrict__ mb1,
                       const float* __restrict__ mw2, const float* __restrict__ mb2,
                       const float* __restrict__ lng, const float* __restrict__ lnb) {
    int g = blockIdx.x, c = threadIdx.x;
    __shared__ float o[128], xa[128], hid[256], red[128];
    o[c] = d_attn_o[g*128 + c];
    __syncthreads();
    float s = out_b[c];
    const float* w = out_w + c*128;
    #pragma unroll 8
    for (int k = 0; k < 128; k++) s += o[k] * w[k];
    xa[c] = s;
    __syncthreads();
    for (int hh = c; hh < 256; hh += 128) {
        float t = mb1[hh];
        #pragma unroll 8
        for (int k = 0; k < 128; k++) t += xa[k] * mw1[k*256 + hh];
        hid[hh] = fmaxf(t, 0.f);
    }
    __syncthreads();
    float m = mb2[c];
    #pragma unroll 8
    for (int k = 0; k < 256; k++) m += hid[k] * mw2[k*128 + c];
    float y = xa[c] + m;
    red[c] = y; __syncthreads();
    for (int o2 = 64; o2 > 0; o2 >>= 1) { if (c < o2) red[c] += red[c + o2]; __syncthreads(); }
    float mu = red[0] * (1.f/128.f);
    __syncthreads();
    float d = y - mu;
    red[c] = d * d; __syncthreads();
    for (int o2 = 64; o2 > 0; o2 >>= 1) { if (c < o2) red[c] += red[c + o2]; __syncthreads(); }
    float var = red[0] * (1.f/128.f);
    float yn = d * rsqrtf(var + LNEPS) * lng[c] + lnb[c];
    atomicAdd(&d_node[c], fmaxf(yn, 0.f));
}

__global__ void k_final(const float* __restrict__ lw, const float* __restrict__ lb,
                        float* __restrict__ out) {
    int t = threadIdx.x;
    __shared__ float nr[128];
    nr[t] = d_node[t];
    __syncthreads();
    if (t < 2) {
        float s = lb[t];
        for (int cc = 0; cc < 128; cc++) s += nr[cc] * lw[cc*2 + t];
        out[t] = s;
    }
}

// ---------------- launch ----------------
extern "C" void kernel_launch(void* const* d_in, const int* in_sizes, int n_in,
                              void* d_out, int out_size) {
    const float* x     = (const float*)d_in[0];
    const int*   ei    = (const int*)  d_in[1];
    const float* W0    = (const float*)d_in[2];
    const float* b0    = (const float*)d_in[3];
    const float* W1    = (const float*)d_in[4];
    const float* b1    = (const float*)d_in[5];
    const float* in_w  = (const float*)d_in[6];
    const float* in_b  = (const float*)d_in[7];
    const float* out_w = (const float*)d_in[8];
    const float* out_b = (const float*)d_in[9];
    const float* lng   = (const float*)d_in[10];
    const float* lnb   = (const float*)d_in[11];
    const float* mw1   = (const float*)d_in[12];
    const float* mb1   = (const float*)d_in[13];
    const float* mw2   = (const float*)d_in[14];
    const float* mb2   = (const float*)d_in[15];
    const float* lw    = (const float*)d_in[16];
    const float* lb    = (const float*)d_in[17];
    float* out = (float*)d_out;

    k_build<<<G, 256>>>(ei);
    k_wprep<<<16, 256>>>(W0, W1);

    // layer 1
    k_gemm_mma<<<1000, 256>>>(x, 0, 0);
    k_gather<<<8000, 256>>>((const float4*)b0, 0);

    // layer 2
    k_gemm_mma<<<1000, 256>>>(nullptr, 1, 1);
    k_gather<<<8000, 256>>>((const float4*)b1, 1);

    // head
    k_qkv<<<G, 384>>>(in_w, in_b);
    k_attn<<<NH, 256>>>();
    k_head<<<G, 128>>>(out_w, out_b, mw1, mb1, mw2, mb2, lng, lnb);
    k_final<<<1, 128>>>(lw, lb, out);
}